// round 15
// baseline (speedup 1.0000x reference)
#include <cuda_runtime.h>
#include <cuda_bf16.h>
#include <cstdint>

#define HWN 4096
#define CCH 128
#define NB 2
#define NHEADS 4
#define HD 32
#define EPSGN 1e-5f
// (1/sqrt(32)) * log2(e)
#define SMSCALE 0.25504733054577454f
#define SPLITS 2

// -------- scratch (device globals) --------
__device__ float g_scale[2][NB][CCH];
__device__ float g_shift[2][NB][CCH];
__device__ __nv_bfloat16 g_in[2][NB][CCH][HWN];   // bf16 copies of x/ctx
__device__ __nv_bfloat16 g_Wouth[CCH][CCH];
__device__ __nv_bfloat16 g_q[NB][CCH][HWN];
__device__ __nv_bfloat16 g_k[NB][CCH][HWN];
__device__ __nv_bfloat16 g_v[NB][CCH][HWN];
__device__ float g_po[SPLITS][NB * NHEADS][32][32][128];  // [sp][bh][dt][ch][row]
__device__ float g_pl[SPLITS][NB * NHEADS][HWN];

#define PACK_BF2(res, lo, hi) \
    asm("cvt.rn.bf16x2.f32 %0, %1, %2;" : "=r"(res) : "f"(hi), "f"(lo))
#define EX2B2(res, in_) \
    asm("ex2.approx.ftz.bf16x2 %0, %1;" : "=r"(res) : "r"(in_))

__device__ __forceinline__ uint32_t smem_u32(const void* p) {
    uint32_t a;
    asm("{ .reg .u64 t; cvta.to.shared.u64 t, %1; cvt.u32.u64 %0, t; }" : "=r"(a) : "l"(p));
    return a;
}
__device__ __forceinline__ void mma16816(float* d, const uint32_t* a, uint32_t b0, uint32_t b1) {
    asm volatile("mma.sync.aligned.m16n8k16.row.col.f32.bf16.bf16.f32 "
        "{%0,%1,%2,%3}, {%4,%5,%6,%7}, {%8,%9}, {%0,%1,%2,%3};"
        : "+f"(d[0]), "+f"(d[1]), "+f"(d[2]), "+f"(d[3])
        : "r"(a[0]), "r"(a[1]), "r"(a[2]), "r"(a[3]), "r"(b0), "r"(b1));
}
#define LDSM_X4(r, a) \
    asm volatile("ldmatrix.sync.aligned.m8n8.x4.shared.b16 {%0,%1,%2,%3}, [%4];" \
        : "=r"((r)[0]), "=r"((r)[1]), "=r"((r)[2]), "=r"((r)[3]) : "r"(a))
#define LDSM_X4T(r, a) \
    asm volatile("ldmatrix.sync.aligned.m8n8.x4.trans.shared.b16 {%0,%1,%2,%3}, [%4];" \
        : "=r"((r)[0]), "=r"((r)[1]), "=r"((r)[2]), "=r"((r)[3]) : "r"(a))
__device__ __forceinline__ void cp16(uint32_t dst, const void* src) {
    asm volatile("cp.async.cg.shared.global [%0], [%1], 16;" :: "r"(dst), "l"(src));
}
#define CP_COMMIT() asm volatile("cp.async.commit_group;" ::: "memory")
#define CP_WAIT0()  asm volatile("cp.async.wait_group 0;" ::: "memory")

// =================== GroupNorm stats + bf16 conversions (512 thr) ===================
__global__ void gn_stats_kernel(const float* __restrict__ x, const float* __restrict__ ctx,
                                const float* __restrict__ gq, const float* __restrict__ bq,
                                const float* __restrict__ gc, const float* __restrict__ bc,
                                const float* __restrict__ Wout) {
    int g = blockIdx.x, b = blockIdx.y, t = blockIdx.z;

    // side job: CTAs (t==1, b==0) cast Wout -> bf16 (each handles 512 floats)
    if (t == 1 && b == 0 && threadIdx.x < 256) {
        int idx = g * 512 + threadIdx.x * 2;
        float2 w = *(const float2*)(Wout + idx);
        uint32_t pk; PACK_BF2(pk, w.x, w.y);
        *(uint32_t*)((uint16_t*)&g_Wouth[0][0] + idx) = pk;
    }

    const float4* src4 = (const float4*)((t == 0 ? x : ctx) + ((size_t)b * CCH + g * 4) * HWN);
    uint16_t* dst = (uint16_t*)&g_in[t][b][g * 4][0];
    float s = 0.f, s2 = 0.f;
    for (int i = threadIdx.x; i < HWN; i += 512) {
        float4 v = src4[i];
        s  += (v.x + v.y) + (v.z + v.w);
        s2 += (v.x * v.x + v.y * v.y) + (v.z * v.z + v.w * v.w);
        uint32_t p0, p1;
        PACK_BF2(p0, v.x, v.y);
        PACK_BF2(p1, v.z, v.w);
        *(uint2*)(dst + i * 4) = make_uint2(p0, p1);
    }
    __shared__ float r1[512], r2[512];
    r1[threadIdx.x] = s; r2[threadIdx.x] = s2;
    __syncthreads();
    for (int st = 256; st > 0; st >>= 1) {
        if (threadIdx.x < st) { r1[threadIdx.x] += r1[threadIdx.x + st]; r2[threadIdx.x] += r2[threadIdx.x + st]; }
        __syncthreads();
    }
    __shared__ float mean_s, rstd_s;
    if (threadIdx.x == 0) {
        float mean = r1[0] * (1.f / 16384.f);
        float var  = r2[0] * (1.f / 16384.f) - mean * mean;
        mean_s = mean; rstd_s = rsqrtf(var + EPSGN);
    }
    __syncthreads();
    if (threadIdx.x < 4) {
        int ch = g * 4 + threadIdx.x;
        float gam = (t == 0 ? gq : gc)[ch];
        float bet = (t == 0 ? bq : bc)[ch];
        float sc = rstd_s * gam;
        g_scale[t][b][ch] = sc;
        g_shift[t][b][ch] = bet - mean_s * sc;
    }
}

// =================== QKV GEMM on HMMA, bf16 inputs via cp.async pipeline ===================
#define WST 136
#define XSTQ 72
#define XQBUF (32 * XSTQ * 2)   // bytes per Xs buffer

__global__ void __launch_bounds__(256) qkv_mma_kernel(const float* __restrict__ Wq,
                                                      const float* __restrict__ Wk,
                                                      const float* __restrict__ Wv) {
    __shared__ __align__(16) uint16_t Ws[128 * WST];
    __shared__ __align__(16) uint16_t Xs[2][32 * XSTQ];
    __shared__ float sbias[128];

    int tid = threadIdx.x, warp = tid >> 5, lane = tid & 31;
    int l4 = lane >> 2, k2 = (lane & 3) * 2;
    int mid = lane >> 3, rr = lane & 7;
    int s0 = blockIdx.x * 64;
    int bm = blockIdx.y, b = bm / 3, m = bm % 3;
    const uint16_t* in = (const uint16_t*)(m == 0 ? &g_in[0][b][0][0] : &g_in[1][b][0][0]);
    const float* Wraw = (m == 0 ? Wq : m == 1 ? Wk : Wv);
    __nv_bfloat16* out = (m == 0 ? &g_q[b][0][0] : m == 1 ? &g_k[b][0][0] : &g_v[b][0][0]);

    int c = tid >> 3, seg = (tid & 7) * 8;
    uint32_t xbase = smem_u32(Xs);

    // ---- prologue: async-load chunk 0 ----
    cp16(xbase + (uint32_t)(c * XSTQ + seg) * 2u, in + (size_t)c * HWN + s0 + seg);
    CP_COMMIT();

    // ---- stage W tile (float4): fold GN scale/shift (and SMSCALE for q) ----
    {
        int o = tid >> 1, part = (tid & 1) * 64;
        const float* wsrc = Wraw + o * CCH + part;
        float bias = 0.f;
        if (m != 2) {
            int t = (m == 0) ? 0 : 1;
            const float* scl = &g_scale[t][b][part];
            const float* shf = &g_shift[t][b][part];
            float msc = (m == 0) ? SMSCALE : 1.f;
#pragma unroll
            for (int i = 0; i < 64; i += 4) {
                float4 w4 = *(const float4*)(wsrc + i);
                float4 s4 = *(const float4*)(scl + i);
                float4 h4 = *(const float4*)(shf + i);
                bias += w4.x * h4.x + w4.y * h4.y + w4.z * h4.z + w4.w * h4.w;
                uint32_t p0, p1;
                PACK_BF2(p0, w4.x * s4.x * msc, w4.y * s4.y * msc);
                PACK_BF2(p1, w4.z * s4.z * msc, w4.w * s4.w * msc);
                *(uint32_t*)&Ws[o * WST + part + i]     = p0;
                *(uint32_t*)&Ws[o * WST + part + i + 2] = p1;
            }
            bias *= msc;
        } else {
#pragma unroll
            for (int i = 0; i < 64; i += 4) {
                float4 w4 = *(const float4*)(wsrc + i);
                uint32_t p0, p1;
                PACK_BF2(p0, w4.x, w4.y);
                PACK_BF2(p1, w4.z, w4.w);
                *(uint32_t*)&Ws[o * WST + part + i]     = p0;
                *(uint32_t*)&Ws[o * WST + part + i + 2] = p1;
            }
        }
        bias += __shfl_xor_sync(0xffffffffu, bias, 1);
        if ((tid & 1) == 0) sbias[o] = bias;
    }
    __syncthreads();

    int o0 = warp * 16;
    uint32_t af[8][4];
#pragma unroll
    for (int kt = 0; kt < 8; kt++) {
        af[kt][0] = *(uint32_t*)&Ws[(o0 + l4) * WST + kt * 16 + k2];
        af[kt][1] = *(uint32_t*)&Ws[(o0 + l4 + 8) * WST + kt * 16 + k2];
        af[kt][2] = *(uint32_t*)&Ws[(o0 + l4) * WST + kt * 16 + k2 + 8];
        af[kt][3] = *(uint32_t*)&Ws[(o0 + l4 + 8) * WST + kt * 16 + k2 + 8];
    }

    float acc[8][4] = {};

#pragma unroll
    for (int c4 = 0; c4 < 4; c4++) {
        int buf = c4 & 1;
        CP_WAIT0();
        __syncthreads();
        if (c4 < 3) {
            cp16(xbase + (uint32_t)(buf ^ 1) * XQBUF + (uint32_t)(c * XSTQ + seg) * 2u,
                 in + (size_t)((c4 + 1) * 32 + c) * HWN + s0 + seg);
        }
        CP_COMMIT();

#pragma unroll
        for (int kt = 0; kt < 2; kt++) {
#pragma unroll
            for (int pp = 0; pp < 4; pp++) {
                int c_row = kt * 16 + (mid & 1) * 8 + rr;
                int s_col = pp * 16 + (mid >> 1) * 8;
                uint32_t bf[4];
                LDSM_X4T(bf, xbase + (uint32_t)buf * XQBUF + (uint32_t)(c_row * XSTQ + s_col) * 2u);
                mma16816(acc[2 * pp],     af[c4 * 2 + kt], bf[0], bf[1]);
                mma16816(acc[2 * pp + 1], af[c4 * 2 + kt], bf[2], bf[3]);
            }
        }
    }

    float b0 = sbias[o0 + l4];
    float b1 = sbias[o0 + l4 + 8];
#pragma unroll
    for (int nt = 0; nt < 8; nt++) {
        int s = s0 + nt * 8 + k2;
        uint32_t lo, hi;
        PACK_BF2(lo, acc[nt][0] + b0, acc[nt][1] + b0);
        PACK_BF2(hi, acc[nt][2] + b1, acc[nt][3] + b1);
        *(uint32_t*)&out[(size_t)(o0 + l4) * HWN + s]     = lo;
        *(uint32_t*)&out[(size_t)(o0 + l4 + 8) * HWN + s] = hi;
    }
}

// =================== flash attention, split-KV x2, bf16x2 ex2, ones-HMMA row sums ===================
#define AST 136
#define TBUF (32 * AST * 2)
#define ONESBF 0x3F803F80u

__global__ void __launch_bounds__(256, 4) attn_mma_kernel() {
    __shared__ __align__(16) uint16_t Ks[2][32 * AST];
    __shared__ __align__(16) uint16_t Vs[2][32 * AST];

    int tid = threadIdx.x, warp = tid >> 5, lane = tid & 31;
    int l4 = lane >> 2, mid = lane >> 3, rr = lane & 7;
    int dt = blockIdx.x, bh = blockIdx.y, sp = blockIdx.z;
    int b = bh >> 2, h = bh & 3;
    int d0 = dt * 128, r0 = warp * 16;

    const uint16_t* Qg = (const uint16_t*)&g_q[b][h * HD][0];
    const uint16_t* Kg = (const uint16_t*)&g_k[b][h * HD][0];
    const uint16_t* Vg = (const uint16_t*)&g_v[b][h * HD][0];

    uint32_t kbase = smem_u32(Ks);
    uint32_t vbase = smem_u32(Vs);
    int sc = tid >> 3, sseg = (tid & 7) * 16;
    int ebase = sp * (HWN / SPLITS);

    // ---- stage Q tile through Ks[0] ----
    {
        const uint16_t* src = Qg + (size_t)sc * HWN + d0 + sseg;
        *(uint4*)&Ks[0][sc * AST + sseg]     = *(const uint4*)(src);
        *(uint4*)&Ks[0][sc * AST + sseg + 8] = *(const uint4*)(src + 8);
    }
    __syncthreads();
    uint32_t qf[2][4];
#pragma unroll
    for (int kt = 0; kt < 2; kt++) {
        int c_row = kt * 16 + (mid >> 1) * 8 + rr;
        int m_col = r0 + (mid & 1) * 8;
        LDSM_X4T(qf[kt], kbase + (uint32_t)(c_row * AST + m_col) * 2u);
    }
    __syncthreads();

    {
        uint32_t kd = kbase + (uint32_t)(sc * AST + sseg) * 2u;
        uint32_t vd = vbase + (uint32_t)(sc * AST + sseg) * 2u;
        cp16(kd,      Kg + (size_t)sc * HWN + ebase + sseg);
        cp16(kd + 16, Kg + (size_t)sc * HWN + ebase + sseg + 8);
        cp16(vd,      Vg + (size_t)sc * HWN + ebase + sseg);
        cp16(vd + 16, Vg + (size_t)sc * HWN + ebase + sseg + 8);
    }
    CP_COMMIT();

    float O[4][4] = {};
    float LS[4] = {};

    for (int it = 0; it < HWN / SPLITS / 128; it++) {
        int buf = it & 1;
        CP_WAIT0();
        __syncthreads();
        if (it + 1 < HWN / SPLITS / 128) {
            int e1 = ebase + (it + 1) * 128;
            uint32_t kd = kbase + (uint32_t)(buf ^ 1) * TBUF + (uint32_t)(sc * AST + sseg) * 2u;
            uint32_t vd = vbase + (uint32_t)(buf ^ 1) * TBUF + (uint32_t)(sc * AST + sseg) * 2u;
            cp16(kd,      Kg + (size_t)sc * HWN + e1 + sseg);
            cp16(kd + 16, Kg + (size_t)sc * HWN + e1 + sseg + 8);
            cp16(vd,      Vg + (size_t)sc * HWN + e1 + sseg);
            cp16(vd + 16, Vg + (size_t)sc * HWN + e1 + sseg + 8);
        }
        CP_COMMIT();

        // ---- MMA1: S[16 x 128] ----
        float S[16][4];
#pragma unroll
        for (int nt = 0; nt < 16; nt++) { S[nt][0] = S[nt][1] = S[nt][2] = S[nt][3] = 0.f; }
        uint32_t kb = kbase + (uint32_t)buf * TBUF;
#pragma unroll
        for (int kt = 0; kt < 2; kt++) {
#pragma unroll
            for (int pp = 0; pp < 8; pp++) {
                int c_row = kt * 16 + (mid & 1) * 8 + rr;
                int n_col = pp * 16 + (mid >> 1) * 8;
                uint32_t bf[4];
                LDSM_X4T(bf, kb + (uint32_t)(c_row * AST + n_col) * 2u);
                mma16816(S[2 * pp],     qf[kt], bf[0], bf[1]);
                mma16816(S[2 * pp + 1], qf[kt], bf[2], bf[3]);
            }
        }

        // ---- softmax: pack S->bf16x2, then 2-wide ex2 ----
        uint32_t pf[8][4];
#pragma unroll
        for (int t = 0; t < 8; t++) {
            uint32_t s0, s1, s2, s3;
            PACK_BF2(s0, S[2 * t][0],     S[2 * t][1]);
            PACK_BF2(s1, S[2 * t][2],     S[2 * t][3]);
            PACK_BF2(s2, S[2 * t + 1][0], S[2 * t + 1][1]);
            PACK_BF2(s3, S[2 * t + 1][2], S[2 * t + 1][3]);
            EX2B2(pf[t][0], s0);
            EX2B2(pf[t][1], s1);
            EX2B2(pf[t][2], s2);
            EX2B2(pf[t][3], s3);
        }

        // ---- MMA2: O += P V^T ; LS += P * ones ----
        uint32_t vb = vbase + (uint32_t)buf * TBUF;
#pragma unroll
        for (int kt = 0; kt < 8; kt++) {
            mma16816(LS, pf[kt], ONESBF, ONESBF);
#pragma unroll
            for (int pp = 0; pp < 2; pp++) {
                int n_row = pp * 16 + (mid >> 1) * 8 + rr;
                int koff  = kt * 16 + (mid & 1) * 8;
                uint32_t bf[4];
                LDSM_X4(bf, vb + (uint32_t)(n_row * AST + koff) * 2u);
                mma16816(O[2 * pp],     pf[kt], bf[0], bf[1]);
                mma16816(O[2 * pp + 1], pf[kt], bf[2], bf[3]);
            }
        }
    }

    // ---- epilogue: transposed partial store [ch][row] ----
    int k2 = (lane & 3) * 2;
    if ((lane & 3) == 0) {
        g_pl[sp][bh][d0 + r0 + l4]     = LS[0];
        g_pl[sp][bh][d0 + r0 + l4 + 8] = LS[2];
    }
    float* po = &g_po[sp][bh][dt][0][0];
#pragma unroll
    for (int nt = 0; nt < 4; nt++) {
        int ch = nt * 8 + k2;
        po[(ch)     * 128 + r0 + l4]     = O[nt][0];
        po[(ch + 1) * 128 + r0 + l4]     = O[nt][1];
        po[(ch)     * 128 + r0 + l4 + 8] = O[nt][2];
        po[(ch + 1) * 128 + r0 + l4 + 8] = O[nt][3];
    }
}

// =================== out projection: 32-col tiles, cp.async W, reg double-buffered combine ===================
#define XSTO 40

__global__ void __launch_bounds__(256) out_proj_mma_kernel(const float* __restrict__ x,
                                                           const float* __restrict__ bout,
                                                           const float* __restrict__ alpha,
                                                           float* __restrict__ y) {
    __shared__ __align__(16) uint16_t Ws[128 * WST];
    __shared__ __align__(16) uint16_t Xs[32 * XSTO];

    int tid = threadIdx.x, warp = tid >> 5, lane = tid & 31;
    int l4 = lane >> 2, k2 = (lane & 3) * 2;
    int mid = lane >> 3, rr = lane & 7;
    int st = blockIdx.x, b = blockIdx.y;
    int dt = st >> 2, quarter = st & 3;
    int s0c = quarter * 32;
    int s0 = dt * 128 + s0c;

    int c = tid >> 3, seg = (tid & 7) * 4;
    uint32_t wsbase = smem_u32(Ws);

    // ---- cp.async Ws from preconverted bf16 Wout ----
    {
        int o = tid >> 1, part = (tid & 1) * 64;
        const uint16_t* wsrc = (const uint16_t*)&g_Wouth[0][0] + o * CCH + part;
#pragma unroll
        for (int i = 0; i < 8; i++)
            cp16(wsbase + (uint32_t)(o * WST + part + i * 8) * 2u, wsrc + i * 8);
    }
    CP_COMMIT();

    // ---- prefetch chunk-0 combine loads (overlaps W cp.async) ----
    float4 fb[2][4];
    {
        int bh = b * NHEADS;
#pragma unroll
        for (int sp = 0; sp < SPLITS; sp++) {
            fb[0][sp * 2 + 0] = *(const float4*)&g_po[sp][bh][dt][c][s0c + seg];
            fb[0][sp * 2 + 1] = *(const float4*)&g_pl[sp][bh][s0 + seg];
        }
    }

    CP_WAIT0();
    __syncthreads();

    int o0 = warp * 16;
    uint32_t af[8][4];
#pragma unroll
    for (int kt = 0; kt < 8; kt++) {
        af[kt][0] = *(uint32_t*)&Ws[(o0 + l4) * WST + kt * 16 + k2];
        af[kt][1] = *(uint32_t*)&Ws[(o0 + l4 + 8) * WST + kt * 16 + k2];
        af[kt][2] = *(uint32_t*)&Ws[(o0 + l4) * WST + kt * 16 + k2 + 8];
        af[kt][3] = *(uint32_t*)&Ws[(o0 + l4 + 8) * WST + kt * 16 + k2 + 8];
    }

    float acc[4][4] = {};
    uint32_t xbase = smem_u32(Xs);

#pragma unroll
    for (int c4 = 0; c4 < 4; c4++) {
        if (c4 < 3) {
            int bh = b * NHEADS + c4 + 1;
            int nb = (c4 + 1) & 1;
#pragma unroll
            for (int sp = 0; sp < SPLITS; sp++) {
                fb[nb][sp * 2 + 0] = *(const float4*)&g_po[sp][bh][dt][c][s0c + seg];
                fb[nb][sp * 2 + 1] = *(const float4*)&g_pl[sp][bh][s0 + seg];
            }
        }
        int bs = c4 & 1;
        uint32_t pk[2];
        {
            float4 v0 = fb[bs][0], v1 = fb[bs][2];
            float4 w0 = fb[bs][1], w1 = fb[bs][3];
            float a0 = v0.x + v1.x, a1 = v0.y + v1.y, a2 = v0.z + v1.z, a3 = v0.w + v1.w;
            float l0 = w0.x + w1.x, l1 = w0.y + w1.y, l2 = w0.z + w1.z, l3 = w0.w + w1.w;
            PACK_BF2(pk[0], a0 * __fdividef(1.f, l0), a1 * __fdividef(1.f, l1));
            PACK_BF2(pk[1], a2 * __fdividef(1.f, l2), a3 * __fdividef(1.f, l3));
        }
        __syncthreads();
        *(uint2*)&Xs[c * XSTO + seg] = make_uint2(pk[0], pk[1]);
        __syncthreads();

#pragma unroll
        for (int kt = 0; kt < 2; kt++) {
#pragma unroll
            for (int pp = 0; pp < 2; pp++) {
                int c_row = kt * 16 + (mid & 1) * 8 + rr;
                int s_col = pp * 16 + (mid >> 1) * 8;
                uint32_t bf[4];
                LDSM_X4T(bf, xbase + (uint32_t)(c_row * XSTO + s_col) * 2u);
                mma16816(acc[2 * pp],     af[c4 * 2 + kt], bf[0], bf[1]);
                mma16816(acc[2 * pp + 1], af[c4 * 2 + kt], bf[2], bf[3]);
            }
        }
    }

    float a = *alpha;
    float b0 = bout[o0 + l4], b1 = bout[o0 + l4 + 8];
    size_t base0 = ((size_t)b * CCH + o0 + l4) * HWN;
    size_t base1 = ((size_t)b * CCH + o0 + l4 + 8) * HWN;
#pragma unroll
    for (int nt = 0; nt < 4; nt++) {
        int s = s0 + nt * 8 + k2;
        float2 x0 = *(const float2*)(x + base0 + s);
        float2 x1 = *(const float2*)(x + base1 + s);
        float2 r0v, r1v;
        r0v.x = x0.x + a * (acc[nt][0] + b0);
        r0v.y = x0.y + a * (acc[nt][1] + b0);
        r1v.x = x1.x + a * (acc[nt][2] + b1);
        r1v.y = x1.y + a * (acc[nt][3] + b1);
        *(float2*)(y + base0 + s) = r0v;
        *(float2*)(y + base1 + s) = r1v;
    }
}

// =================== launch ===================
extern "C" void kernel_launch(void* const* d_in, const int* in_sizes, int n_in,
                              void* d_out, int out_size) {
    const float* x    = (const float*)d_in[0];
    const float* ctx  = (const float*)d_in[1];
    const float* gq   = (const float*)d_in[2];
    const float* bq   = (const float*)d_in[3];
    const float* gctx = (const float*)d_in[4];
    const float* bctx = (const float*)d_in[5];
    const float* Wq   = (const float*)d_in[6];
    const float* Wk   = (const float*)d_in[7];
    const float* Wv   = (const float*)d_in[8];
    const float* Wout = (const float*)d_in[9];
    const float* bout = (const float*)d_in[10];
    const float* alpha= (const float*)d_in[11];
    float* y = (float*)d_out;

    static bool attr_done = false;
    if (!attr_done) {
        cudaFuncSetAttribute(attn_mma_kernel, cudaFuncAttributePreferredSharedMemoryCarveout, 100);
        cudaFuncSetAttribute(qkv_mma_kernel, cudaFuncAttributePreferredSharedMemoryCarveout, 100);
        cudaFuncSetAttribute(out_proj_mma_kernel, cudaFuncAttributePreferredSharedMemoryCarveout, 100);
        attr_done = true;
    }

    gn_stats_kernel<<<dim3(32, NB, 2), 512>>>(x, ctx, gq, bq, gctx, bctx, Wout);
    qkv_mma_kernel<<<dim3(64, NB * 3), 256>>>(Wq, Wk, Wv);
    attn_mma_kernel<<<dim3(32, NB * NHEADS, SPLITS), 256>>>();
    out_proj_mma_kernel<<<dim3(128, NB), 256>>>(x, bout, alpha, y);
}

// round 17
// speedup vs baseline: 1.0886x; 1.0886x over previous
#include <cuda_runtime.h>
#include <cuda_bf16.h>
#include <cstdint>

#define HWN 4096
#define CCH 128
#define NB 2
#define NHEADS 4
#define HD 32
#define EPSGN 1e-5f
// (1/sqrt(32)) * log2(e)
#define SMSCALE 0.25504733054577454f
#define SPLITS 2

// -------- scratch (device globals) --------
__device__ float g_scale[2][NB][CCH];
__device__ float g_shift[2][NB][CCH];
__device__ float g_effB[NB][3][CCH];
__device__ __nv_bfloat16 g_effWh[NB][3][CCH][CCH];
__device__ __nv_bfloat16 g_in[2][NB][CCH][HWN];   // bf16 copies of x/ctx
__device__ __nv_bfloat16 g_Wouth[CCH][CCH];
__device__ __nv_bfloat16 g_q[NB][CCH][HWN];
__device__ __nv_bfloat16 g_k[NB][CCH][HWN];
__device__ __nv_bfloat16 g_v[NB][CCH][HWN];
__device__ float g_po[SPLITS][NB * NHEADS][32][32][128];  // [sp][bh][dt][ch][row]
__device__ float g_pl[SPLITS][NB * NHEADS][HWN];

#define PACK_BF2(res, lo, hi) \
    asm("cvt.rn.bf16x2.f32 %0, %1, %2;" : "=r"(res) : "f"(hi), "f"(lo))
#define EX2B2(res, in_) \
    asm("ex2.approx.ftz.bf16x2 %0, %1;" : "=r"(res) : "r"(in_))
#define GRID_WAIT() asm volatile("griddepcontrol.wait;" ::: "memory")

__device__ __forceinline__ uint32_t smem_u32(const void* p) {
    uint32_t a;
    asm("{ .reg .u64 t; cvta.to.shared.u64 t, %1; cvt.u32.u64 %0, t; }" : "=r"(a) : "l"(p));
    return a;
}
__device__ __forceinline__ void mma16816(float* d, const uint32_t* a, uint32_t b0, uint32_t b1) {
    asm volatile("mma.sync.aligned.m16n8k16.row.col.f32.bf16.bf16.f32 "
        "{%0,%1,%2,%3}, {%4,%5,%6,%7}, {%8,%9}, {%0,%1,%2,%3};"
        : "+f"(d[0]), "+f"(d[1]), "+f"(d[2]), "+f"(d[3])
        : "r"(a[0]), "r"(a[1]), "r"(a[2]), "r"(a[3]), "r"(b0), "r"(b1));
}
#define LDSM_X4(r, a) \
    asm volatile("ldmatrix.sync.aligned.m8n8.x4.shared.b16 {%0,%1,%2,%3}, [%4];" \
        : "=r"((r)[0]), "=r"((r)[1]), "=r"((r)[2]), "=r"((r)[3]) : "r"(a))
#define LDSM_X4T(r, a) \
    asm volatile("ldmatrix.sync.aligned.m8n8.x4.trans.shared.b16 {%0,%1,%2,%3}, [%4];" \
        : "=r"((r)[0]), "=r"((r)[1]), "=r"((r)[2]), "=r"((r)[3]) : "r"(a))
__device__ __forceinline__ void cp16(uint32_t dst, const void* src) {
    asm volatile("cp.async.cg.shared.global [%0], [%1], 16;" :: "r"(dst), "l"(src));
}
#define CP_COMMIT() asm volatile("cp.async.commit_group;" ::: "memory")
#define CP_WAIT0()  asm volatile("cp.async.wait_group 0;" ::: "memory")

// =================== GroupNorm stats + bf16 conversions (512 thr) ===================
__global__ void gn_stats_kernel(const float* __restrict__ x, const float* __restrict__ ctx,
                                const float* __restrict__ gq, const float* __restrict__ bq,
                                const float* __restrict__ gc, const float* __restrict__ bc,
                                const float* __restrict__ Wout) {
    int g = blockIdx.x, b = blockIdx.y, t = blockIdx.z;

    if (t == 1 && b == 0 && threadIdx.x < 256) {
        int idx = g * 512 + threadIdx.x * 2;
        float2 w = *(const float2*)(Wout + idx);
        uint32_t pk; PACK_BF2(pk, w.x, w.y);
        *(uint32_t*)((uint16_t*)&g_Wouth[0][0] + idx) = pk;
    }

    const float4* src4 = (const float4*)((t == 0 ? x : ctx) + ((size_t)b * CCH + g * 4) * HWN);
    uint16_t* dst = (uint16_t*)&g_in[t][b][g * 4][0];
    float s = 0.f, s2 = 0.f;
    for (int i = threadIdx.x; i < HWN; i += 512) {
        float4 v = src4[i];
        s  += (v.x + v.y) + (v.z + v.w);
        s2 += (v.x * v.x + v.y * v.y) + (v.z * v.z + v.w * v.w);
        uint32_t p0, p1;
        PACK_BF2(p0, v.x, v.y);
        PACK_BF2(p1, v.z, v.w);
        *(uint2*)(dst + i * 4) = make_uint2(p0, p1);
    }
    __shared__ float r1[512], r2[512];
    r1[threadIdx.x] = s; r2[threadIdx.x] = s2;
    __syncthreads();
    for (int st = 256; st > 0; st >>= 1) {
        if (threadIdx.x < st) { r1[threadIdx.x] += r1[threadIdx.x + st]; r2[threadIdx.x] += r2[threadIdx.x + st]; }
        __syncthreads();
    }
    __shared__ float mean_s, rstd_s;
    if (threadIdx.x == 0) {
        float mean = r1[0] * (1.f / 16384.f);
        float var  = r2[0] * (1.f / 16384.f) - mean * mean;
        mean_s = mean; rstd_s = rsqrtf(var + EPSGN);
    }
    __syncthreads();
    if (threadIdx.x < 4) {
        int ch = g * 4 + threadIdx.x;
        float gam = (t == 0 ? gq : gc)[ch];
        float bet = (t == 0 ? bq : bc)[ch];
        float sc = rstd_s * gam;
        g_scale[t][b][ch] = sc;
        g_shift[t][b][ch] = bet - mean_s * sc;
    }
}

// =================== effective weights (once per b,m) ===================
__global__ void eff_weights_kernel(const float* __restrict__ Wq, const float* __restrict__ Wk,
                                   const float* __restrict__ Wv) {
    GRID_WAIT();
    int o = blockIdx.x, m = blockIdx.y, b = blockIdx.z;
    int c = threadIdx.x;
    const float* W = (m == 0 ? Wq : m == 1 ? Wk : Wv);
    float w = W[o * CCH + c];
    float sc = 1.f, sh = 0.f;
    if (m == 0)      { sc = g_scale[0][b][c]; sh = g_shift[0][b][c]; }
    else if (m == 1) { sc = g_scale[1][b][c]; sh = g_shift[1][b][c]; }
    float msc = (m == 0) ? SMSCALE : 1.f;
    g_effWh[b][m][o][c] = __float2bfloat16(w * sc * msc);
    __shared__ float red[128];
    red[c] = w * sh;
    __syncthreads();
    for (int st = 64; st > 0; st >>= 1) {
        if (c < st) red[c] += red[c + st];
        __syncthreads();
    }
    if (c == 0) g_effB[b][m][o] = red[0] * msc;
}

// =================== QKV GEMM on HMMA, all-bf16 cp.async pipeline ===================
#define WST 136
#define XSTQ 72
#define XQBUF (32 * XSTQ * 2)

__global__ void __launch_bounds__(256) qkv_mma_kernel() {
    __shared__ __align__(16) uint16_t Ws[128 * WST];
    __shared__ __align__(16) uint16_t Xs[2][32 * XSTQ];

    int tid = threadIdx.x, warp = tid >> 5, lane = tid & 31;
    int l4 = lane >> 2, k2 = (lane & 3) * 2;
    int mid = lane >> 3, rr = lane & 7;
    int s0 = blockIdx.x * 64;
    int bm = blockIdx.y, b = bm / 3, m = bm % 3;

    GRID_WAIT();

    const uint16_t* in = (const uint16_t*)(m == 0 ? &g_in[0][b][0][0] : &g_in[1][b][0][0]);
    __nv_bfloat16* out = (m == 0 ? &g_q[b][0][0] : m == 1 ? &g_k[b][0][0] : &g_v[b][0][0]);

    int c = tid >> 3, seg = (tid & 7) * 8;
    uint32_t xbase = smem_u32(Xs);
    uint32_t wsbase = smem_u32(Ws);

    // ---- prologue: cp.async Weff tile + chunk 0 ----
    {
        int o = tid >> 1, part = (tid & 1) * 64;
        const uint16_t* wsrc = (const uint16_t*)&g_effWh[b][m][o][part];
#pragma unroll
        for (int i = 0; i < 8; i++)
            cp16(wsbase + (uint32_t)(o * WST + part + i * 8) * 2u, wsrc + i * 8);
    }
    cp16(xbase + (uint32_t)(c * XSTQ + seg) * 2u, in + (size_t)c * HWN + s0 + seg);
    CP_COMMIT();
    CP_WAIT0();
    __syncthreads();

    int o0 = warp * 16;
    uint32_t af[8][4];
#pragma unroll
    for (int kt = 0; kt < 8; kt++) {
        af[kt][0] = *(uint32_t*)&Ws[(o0 + l4) * WST + kt * 16 + k2];
        af[kt][1] = *(uint32_t*)&Ws[(o0 + l4 + 8) * WST + kt * 16 + k2];
        af[kt][2] = *(uint32_t*)&Ws[(o0 + l4) * WST + kt * 16 + k2 + 8];
        af[kt][3] = *(uint32_t*)&Ws[(o0 + l4 + 8) * WST + kt * 16 + k2 + 8];
    }

    float acc[8][4] = {};

#pragma unroll
    for (int c4 = 0; c4 < 4; c4++) {
        int buf = c4 & 1;
        if (c4 > 0) { CP_WAIT0(); __syncthreads(); }
        if (c4 < 3) {
            cp16(xbase + (uint32_t)(buf ^ 1) * XQBUF + (uint32_t)(c * XSTQ + seg) * 2u,
                 in + (size_t)((c4 + 1) * 32 + c) * HWN + s0 + seg);
        }
        CP_COMMIT();

#pragma unroll
        for (int kt = 0; kt < 2; kt++) {
#pragma unroll
            for (int pp = 0; pp < 4; pp++) {
                int c_row = kt * 16 + (mid & 1) * 8 + rr;
                int s_col = pp * 16 + (mid >> 1) * 8;
                uint32_t bf[4];
                LDSM_X4T(bf, xbase + (uint32_t)buf * XQBUF + (uint32_t)(c_row * XSTQ + s_col) * 2u);
                mma16816(acc[2 * pp],     af[c4 * 2 + kt], bf[0], bf[1]);
                mma16816(acc[2 * pp + 1], af[c4 * 2 + kt], bf[2], bf[3]);
            }
        }
    }

    float b0 = g_effB[b][m][o0 + l4];
    float b1 = g_effB[b][m][o0 + l4 + 8];
#pragma unroll
    for (int nt = 0; nt < 8; nt++) {
        int s = s0 + nt * 8 + k2;
        uint32_t lo, hi;
        PACK_BF2(lo, acc[nt][0] + b0, acc[nt][1] + b0);
        PACK_BF2(hi, acc[nt][2] + b1, acc[nt][3] + b1);
        *(uint32_t*)&out[(size_t)(o0 + l4) * HWN + s]     = lo;
        *(uint32_t*)&out[(size_t)(o0 + l4 + 8) * HWN + s] = hi;
    }
}

// =================== flash attention, split-KV x2, bf16x2 ex2, ones-HMMA row sums ===================
#define AST 136
#define TBUF (32 * AST * 2)
#define ONESBF 0x3F803F80u

__global__ void __launch_bounds__(256, 4) attn_mma_kernel() {
    __shared__ __align__(16) uint16_t Ks[2][32 * AST];
    __shared__ __align__(16) uint16_t Vs[2][32 * AST];

    int tid = threadIdx.x, warp = tid >> 5, lane = tid & 31;
    int l4 = lane >> 2, mid = lane >> 3, rr = lane & 7;
    int dt = blockIdx.x, bh = blockIdx.y, sp = blockIdx.z;
    int b = bh >> 2, h = bh & 3;
    int d0 = dt * 128, r0 = warp * 16;

    GRID_WAIT();

    const uint16_t* Qg = (const uint16_t*)&g_q[b][h * HD][0];
    const uint16_t* Kg = (const uint16_t*)&g_k[b][h * HD][0];
    const uint16_t* Vg = (const uint16_t*)&g_v[b][h * HD][0];

    uint32_t kbase = smem_u32(Ks);
    uint32_t vbase = smem_u32(Vs);
    int sc = tid >> 3, sseg = (tid & 7) * 16;
    int ebase = sp * (HWN / SPLITS);

    // ---- stage Q tile through Ks[0] ----
    {
        const uint16_t* src = Qg + (size_t)sc * HWN + d0 + sseg;
        *(uint4*)&Ks[0][sc * AST + sseg]     = *(const uint4*)(src);
        *(uint4*)&Ks[0][sc * AST + sseg + 8] = *(const uint4*)(src + 8);
    }
    __syncthreads();
    uint32_t qf[2][4];
#pragma unroll
    for (int kt = 0; kt < 2; kt++) {
        int c_row = kt * 16 + (mid >> 1) * 8 + rr;
        int m_col = r0 + (mid & 1) * 8;
        LDSM_X4T(qf[kt], kbase + (uint32_t)(c_row * AST + m_col) * 2u);
    }
    __syncthreads();

    {
        uint32_t kd = kbase + (uint32_t)(sc * AST + sseg) * 2u;
        uint32_t vd = vbase + (uint32_t)(sc * AST + sseg) * 2u;
        cp16(kd,      Kg + (size_t)sc * HWN + ebase + sseg);
        cp16(kd + 16, Kg + (size_t)sc * HWN + ebase + sseg + 8);
        cp16(vd,      Vg + (size_t)sc * HWN + ebase + sseg);
        cp16(vd + 16, Vg + (size_t)sc * HWN + ebase + sseg + 8);
    }
    CP_COMMIT();

    float O[4][4] = {};
    float LS[4] = {};

    for (int it = 0; it < HWN / SPLITS / 128; it++) {
        int buf = it & 1;
        CP_WAIT0();
        __syncthreads();
        if (it + 1 < HWN / SPLITS / 128) {
            int e1 = ebase + (it + 1) * 128;
            uint32_t kd = kbase + (uint32_t)(buf ^ 1) * TBUF + (uint32_t)(sc * AST + sseg) * 2u;
            uint32_t vd = vbase + (uint32_t)(buf ^ 1) * TBUF + (uint32_t)(sc * AST + sseg) * 2u;
            cp16(kd,      Kg + (size_t)sc * HWN + e1 + sseg);
            cp16(kd + 16, Kg + (size_t)sc * HWN + e1 + sseg + 8);
            cp16(vd,      Vg + (size_t)sc * HWN + e1 + sseg);
            cp16(vd + 16, Vg + (size_t)sc * HWN + e1 + sseg + 8);
        }
        CP_COMMIT();

        // ---- MMA1: S[16 x 128] ----
        float S[16][4];
#pragma unroll
        for (int nt = 0; nt < 16; nt++) { S[nt][0] = S[nt][1] = S[nt][2] = S[nt][3] = 0.f; }
        uint32_t kb = kbase + (uint32_t)buf * TBUF;
#pragma unroll
        for (int kt = 0; kt < 2; kt++) {
#pragma unroll
            for (int pp = 0; pp < 8; pp++) {
                int c_row = kt * 16 + (mid & 1) * 8 + rr;
                int n_col = pp * 16 + (mid >> 1) * 8;
                uint32_t bf[4];
                LDSM_X4T(bf, kb + (uint32_t)(c_row * AST + n_col) * 2u);
                mma16816(S[2 * pp],     qf[kt], bf[0], bf[1]);
                mma16816(S[2 * pp + 1], qf[kt], bf[2], bf[3]);
            }
        }

        // ---- softmax: pack S->bf16x2, then 2-wide ex2 ----
        uint32_t pf[8][4];
#pragma unroll
        for (int t = 0; t < 8; t++) {
            uint32_t s0, s1, s2, s3;
            PACK_BF2(s0, S[2 * t][0],     S[2 * t][1]);
            PACK_BF2(s1, S[2 * t][2],     S[2 * t][3]);
            PACK_BF2(s2, S[2 * t + 1][0], S[2 * t + 1][1]);
            PACK_BF2(s3, S[2 * t + 1][2], S[2 * t + 1][3]);
            EX2B2(pf[t][0], s0);
            EX2B2(pf[t][1], s1);
            EX2B2(pf[t][2], s2);
            EX2B2(pf[t][3], s3);
        }

        // ---- MMA2: O += P V^T ; LS += P * ones ----
        uint32_t vb = vbase + (uint32_t)buf * TBUF;
#pragma unroll
        for (int kt = 0; kt < 8; kt++) {
            mma16816(LS, pf[kt], ONESBF, ONESBF);
#pragma unroll
            for (int pp = 0; pp < 2; pp++) {
                int n_row = pp * 16 + (mid >> 1) * 8 + rr;
                int koff  = kt * 16 + (mid & 1) * 8;
                uint32_t bf[4];
                LDSM_X4(bf, vb + (uint32_t)(n_row * AST + koff) * 2u);
                mma16816(O[2 * pp],     pf[kt], bf[0], bf[1]);
                mma16816(O[2 * pp + 1], pf[kt], bf[2], bf[3]);
            }
        }
    }

    // ---- epilogue: transposed partial store [ch][row] ----
    int k2 = (lane & 3) * 2;
    if ((lane & 3) == 0) {
        g_pl[sp][bh][d0 + r0 + l4]     = LS[0];
        g_pl[sp][bh][d0 + r0 + l4 + 8] = LS[2];
    }
    float* po = &g_po[sp][bh][dt][0][0];
#pragma unroll
    for (int nt = 0; nt < 4; nt++) {
        int ch = nt * 8 + k2;
        po[(ch)     * 128 + r0 + l4]     = O[nt][0];
        po[(ch + 1) * 128 + r0 + l4]     = O[nt][1];
        po[(ch)     * 128 + r0 + l4 + 8] = O[nt][2];
        po[(ch + 1) * 128 + r0 + l4 + 8] = O[nt][3];
    }
}

// =================== out projection: 64-col tiles; W staged pre-wait (PDL) ===================
#define XST2 72

__global__ void __launch_bounds__(256) out_proj_mma_kernel(const float* __restrict__ x,
                                                           const float* __restrict__ bout,
                                                           const float* __restrict__ alpha,
                                                           float* __restrict__ y) {
    __shared__ __align__(16) uint16_t Ws[128 * WST];
    __shared__ __align__(16) uint16_t Xs[32 * XST2];

    int tid = threadIdx.x, warp = tid >> 5, lane = tid & 31;
    int l4 = lane >> 2, k2 = (lane & 3) * 2;
    int mid = lane >> 3, rr = lane & 7;
    int st = blockIdx.x, b = blockIdx.y;
    int dt = st >> 1, half = st & 1;
    int s0c = half * 64;
    int s0 = dt * 128 + s0c;

    int c = tid >> 3, seg = (tid & 7) * 8;
    uint32_t wsbase = smem_u32(Ws);

    // ---- PRE-WAIT: stage W (g_Wouth written 2 kernels back -> complete) + af ----
    {
        int o = tid >> 1, part = (tid & 1) * 64;
        const uint16_t* wsrc = (const uint16_t*)&g_Wouth[0][0] + o * CCH + part;
#pragma unroll
        for (int i = 0; i < 8; i++)
            cp16(wsbase + (uint32_t)(o * WST + part + i * 8) * 2u, wsrc + i * 8);
    }
    CP_COMMIT();
    CP_WAIT0();
    __syncthreads();

    int o0 = warp * 16;
    uint32_t af[8][4];
#pragma unroll
    for (int kt = 0; kt < 8; kt++) {
        af[kt][0] = *(uint32_t*)&Ws[(o0 + l4) * WST + kt * 16 + k2];
        af[kt][1] = *(uint32_t*)&Ws[(o0 + l4 + 8) * WST + kt * 16 + k2];
        af[kt][2] = *(uint32_t*)&Ws[(o0 + l4) * WST + kt * 16 + k2 + 8];
        af[kt][3] = *(uint32_t*)&Ws[(o0 + l4 + 8) * WST + kt * 16 + k2 + 8];
    }

    GRID_WAIT();   // now wait for attention's partials

    float4 fb[2][8];
    {
        int bh = b * NHEADS;
#pragma unroll
        for (int sp = 0; sp < SPLITS; sp++) {
            const float* p  = &g_po[sp][bh][dt][c][s0c + seg];
            const float* pl = &g_pl[sp][bh][s0 + seg];
            fb[0][sp * 4 + 0] = *(const float4*)(p);
            fb[0][sp * 4 + 1] = *(const float4*)(p + 4);
            fb[0][sp * 4 + 2] = *(const float4*)(pl);
            fb[0][sp * 4 + 3] = *(const float4*)(pl + 4);
        }
    }

    float acc[8][4] = {};
    uint32_t xbase = smem_u32(Xs);

#pragma unroll
    for (int c4 = 0; c4 < 4; c4++) {
        if (c4 < 3) {
            int bh = b * NHEADS + c4 + 1;
            int nb = (c4 + 1) & 1;
#pragma unroll
            for (int sp = 0; sp < SPLITS; sp++) {
                const float* p  = &g_po[sp][bh][dt][c][s0c + seg];
                const float* pl = &g_pl[sp][bh][s0 + seg];
                fb[nb][sp * 4 + 0] = *(const float4*)(p);
                fb[nb][sp * 4 + 1] = *(const float4*)(p + 4);
                fb[nb][sp * 4 + 2] = *(const float4*)(pl);
                fb[nb][sp * 4 + 3] = *(const float4*)(pl + 4);
            }
        }
        int bs = c4 & 1;
        uint32_t pk[4];
#pragma unroll
        for (int q = 0; q < 2; q++) {
            float4 v0 = fb[bs][q],     v1 = fb[bs][4 + q];
            float4 w0 = fb[bs][2 + q], w1 = fb[bs][6 + q];
            float a0 = v0.x + v1.x, a1 = v0.y + v1.y, a2 = v0.z + v1.z, a3 = v0.w + v1.w;
            float l0 = w0.x + w1.x, l1 = w0.y + w1.y, l2 = w0.z + w1.z, l3 = w0.w + w1.w;
            PACK_BF2(pk[q * 2],     a0 * __fdividef(1.f, l0), a1 * __fdividef(1.f, l1));
            PACK_BF2(pk[q * 2 + 1], a2 * __fdividef(1.f, l2), a3 * __fdividef(1.f, l3));
        }
        __syncthreads();
        *(uint4*)&Xs[c * XST2 + seg] = make_uint4(pk[0], pk[1], pk[2], pk[3]);
        __syncthreads();

#pragma unroll
        for (int kt = 0; kt < 2; kt++) {
#pragma unroll
            for (int pp = 0; pp < 4; pp++) {
                int c_row = kt * 16 + (mid & 1) * 8 + rr;
                int s_col = pp * 16 + (mid >> 1) * 8;
                uint32_t bf[4];
                LDSM_X4T(bf, xbase + (uint32_t)(c_row * XST2 + s_col) * 2u);
                mma16816(acc[2 * pp],     af[c4 * 2 + kt], bf[0], bf[1]);
                mma16816(acc[2 * pp + 1], af[c4 * 2 + kt], bf[2], bf[3]);
            }
        }
    }

    float a = *alpha;
    float b0 = bout[o0 + l4], b1 = bout[o0 + l4 + 8];
    size_t base0 = ((size_t)b * CCH + o0 + l4) * HWN;
    size_t base1 = ((size_t)b * CCH + o0 + l4 + 8) * HWN;
#pragma unroll
    for (int nt = 0; nt < 8; nt++) {
        int s = s0 + nt * 8 + k2;
        float2 x0 = *(const float2*)(x + base0 + s);
        float2 x1 = *(const float2*)(x + base1 + s);
        float2 r0v, r1v;
        r0v.x = x0.x + a * (acc[nt][0] + b0);
        r0v.y = x0.y + a * (acc[nt][1] + b0);
        r1v.x = x1.x + a * (acc[nt][2] + b1);
        r1v.y = x1.y + a * (acc[nt][3] + b1);
        *(float2*)(y + base0 + s) = r0v;
        *(float2*)(y + base1 + s) = r1v;
    }
}

// =================== launch (PDL-chained) ===================
template <typename... Args>
static void launch_pdl(dim3 grid, dim3 block, void (*kern)(Args...), Args... args) {
    cudaLaunchConfig_t cfg = {};
    cfg.gridDim = grid;
    cfg.blockDim = block;
    cfg.stream = 0;
    cudaLaunchAttribute at[1];
    at[0].id = cudaLaunchAttributeProgrammaticStreamSerialization;
    at[0].val.programmaticStreamSerializationAllowed = 1;
    cfg.attrs = at;
    cfg.numAttrs = 1;
    cudaLaunchKernelEx(&cfg, kern, args...);
}

extern "C" void kernel_launch(void* const* d_in, const int* in_sizes, int n_in,
                              void* d_out, int out_size) {
    const float* x    = (const float*)d_in[0];
    const float* ctx  = (const float*)d_in[1];
    const float* gq   = (const float*)d_in[2];
    const float* bq   = (const float*)d_in[3];
    const float* gctx = (const float*)d_in[4];
    const float* bctx = (const float*)d_in[5];
    const float* Wq   = (const float*)d_in[6];
    const float* Wk   = (const float*)d_in[7];
    const float* Wv   = (const float*)d_in[8];
    const float* Wout = (const float*)d_in[9];
    const float* bout = (const float*)d_in[10];
    const float* alpha= (const float*)d_in[11];
    float* y = (float*)d_out;

    static bool attr_done = false;
    if (!attr_done) {
        cudaFuncSetAttribute(attn_mma_kernel, cudaFuncAttributePreferredSharedMemoryCarveout, 100);
        cudaFuncSetAttribute(qkv_mma_kernel, cudaFuncAttributePreferredSharedMemoryCarveout, 100);
        cudaFuncSetAttribute(out_proj_mma_kernel, cudaFuncAttributePreferredSharedMemoryCarveout, 100);
        attr_done = true;
    }

    gn_stats_kernel<<<dim3(32, NB, 2), 512>>>(x, ctx, gq, bq, gctx, bctx, Wout);
    launch_pdl(dim3(CCH, 3, NB), dim3(128), eff_weights_kernel, Wq, Wk, Wv);
    launch_pdl(dim3(64, NB * 3), dim3(256), qkv_mma_kernel);
    launch_pdl(dim3(32, NB * NHEADS, SPLITS), dim3(256), attn_mma_kernel);
    launch_pdl(dim3(64, NB), dim3(256), out_proj_mma_kernel, x, bout, alpha, y);
}